// round 13
// baseline (speedup 1.0000x reference)
#include <cuda_runtime.h>

#define HH 32
#define WW 32
#define BB 16
#define NPOS 512
#define PIX 8              // pixels per block (contiguous in one row)
#define THREADS 512
#define GRID 128
#define NLAYERS 4
#define AROW 68            // floats per A-octant (64 data + 4 pad)
#define SROW 548           // floats per pixel row (8*68=544 + 4 pad)
#define LHW (NPOS * HH * WW)
#define VROW 12            // window smem: cols per row (10 used)
#define VBAT 36            // window smem: floats per batch (3*12)

// 3 state buffers (no WAR hazards) — no device allocation allowed.
__device__ float g_state[3][BB * HH * WW];
// Replay-safe sync state: PER-LAYER monotonic counters (never reset).
__device__ unsigned g_epoch[NLAYERS][GRID];
__device__ unsigned g_flag[NLAYERS][GRID];

__device__ __forceinline__ float sigmoidf(float x) {
    return __fdividef(1.0f, 1.0f + __expf(-x));
}

__device__ __forceinline__ void triple8(float va, float vb, float vc, float* P) {
    float ca = 1.0f - va, cb = 1.0f - vb, cc = 1.0f - vc;
    float t0 = cb * cc, t1 = cb * vc, t2 = vb * cc, t3 = vb * vc;
    P[0] = ca * t0; P[1] = ca * t1; P[2] = ca * t2; P[3] = ca * t3;
    P[4] = va * t0; P[5] = va * t1; P[6] = va * t2; P[7] = va * t3;
}

__global__ __launch_bounds__(THREADS, 2)
void asic_layer(const float* __restrict__ src,   // (B,H,W) previous state
                const float* __restrict__ tg,    // (NPOS,H,W) this layer's gates
                float* __restrict__ dst,         // (B,H,W)
                int L)                           // layer index 0..3
{
    __shared__ __align__(16) float s_s[PIX * SROW];      // sigmoid(gates)
    __shared__ __align__(16) float s_v[BB * VBAT];       // state window halo
    __shared__ unsigned s_ep;

#if __CUDA_ARCH__ >= 900
    // Let the next layer's kernel launch immediately; ordering is carried by
    // the per-tile flags below, NOT by stream serialization.
    cudaTriggerProgrammaticLaunchCompletion();
#endif

    const int tid = threadIdx.x;
    const int bid = blockIdx.x;
    const int pixBase = bid * PIX;
    const int hB = pixBase >> 5;         // tile row
    const int w0 = pixBase & 31;         // tile first col

    // Per-LAYER monotonic epoch: layer L's k-th launch -> epoch k, for every
    // block, independent of cross-kernel interleaving. Producers and consumers
    // therefore agree exactly per replay.
    if (tid == 0) s_ep = atomicAdd(&g_epoch[L][bid], 1u) + 1u;

    // ---- thread mapping: oct(8) x batch-pair(8) x pixel(8) ----
    const int oct  = tid & 7;
    const int bp   = (tid >> 3) & 7;
    const int pixL = tid >> 6;
    const int pixel = pixBase + pixL;
    const int b0 = bp, b1 = bp + 8;

    // My 9 producer tiles (rows hB..hB+2, col-quarters q-1..q+1, wrapped).
    int nbrId = 0;
    if (tid < 9) {
        int q = bid & 3;
        int rr = (hB + tid / 3) & 31;
        int qq = (q + (tid % 3) - 1) & 3;
        nbrId = rr * 4 + qq;
    }

    // ================= state-INDEPENDENT prologue (overlaps prev layer) ======
    const int p0  = tid >> 1;
    const int ih0 = (tid & 1) * 4;
    float4 g0 = *(const float4*)(tg + p0 * (HH * WW) + pixBase + ih0);
    const int c1  = tid + THREADS;
    const int p1  = c1 >> 1;
    const int ih1 = (c1 & 1) * 4;
    float4 g1 = *(const float4*)(tg + p1 * (HH * WW) + pixBase + ih1);

    {
        int base = (p0 >> 6) * AROW + (p0 & 63);
        s_s[(ih0 + 0) * SROW + base] = sigmoidf(g0.x);
        s_s[(ih0 + 1) * SROW + base] = sigmoidf(g0.y);
        s_s[(ih0 + 2) * SROW + base] = sigmoidf(g0.z);
        s_s[(ih0 + 3) * SROW + base] = sigmoidf(g0.w);
        base = (p1 >> 6) * AROW + (p1 & 63);
        s_s[(ih1 + 0) * SROW + base] = sigmoidf(g1.x);
        s_s[(ih1 + 1) * SROW + base] = sigmoidf(g1.y);
        s_s[(ih1 + 2) * SROW + base] = sigmoidf(g1.z);
        s_s[(ih1 + 3) * SROW + base] = sigmoidf(g1.w);
    }
    __syncthreads();                     // s_ep + gate staging visible

    // ================= wait on my 9 producer tiles only ======================
    const unsigned target = s_ep;        // == this replay's index for layer L
    if (L > 0) {
        if (tid < 9) {
            // Producer layer L-1 publishes ITS epoch, which equals `target`.
            while (*((volatile unsigned*)&g_flag[L - 1][nbrId]) < target) { }
            __threadfence();
        }
        __syncthreads();
    }

    // ================= state-DEPENDENT part ==================================
    if (tid < BB * 30) {
        int b   = tid / 30;
        int rem = tid % 30;
        int r   = rem / 10;
        int c   = rem % 10;
        int row = (hB + r) & 31;
        int col = (w0 - 1 + c) & 31;
        s_v[b * VBAT + r * VROW + c] = __ldcg(src + b * (HH * WW) + row * WW + col);
    }
    __syncthreads();

    float v0[9], v1[9];
#pragma unroll
    for (int i0 = 0; i0 < 3; i0++) {
#pragma unroll
        for (int i1 = 0; i1 < 3; i1++) {
            int c = i0 * VROW + pixL + i1;
            v0[i0 * 3 + i1] = s_v[b0 * VBAT + c];
            v1[i0 * 3 + i1] = s_v[b1 * VBAT + c];
        }
    }

    // A = j>>6 (m0..m2, fixed = oct), B = (j>>3)&7 (m3..m5), C = j&7 (m6..m8)
    float PB0[8], PB1[8], PC0[8], PC1[8];
    triple8(v0[3], v0[4], v0[5], PB0);
    triple8(v0[6], v0[7], v0[8], PC0);
    triple8(v1[3], v1[4], v1[5], PB1);
    triple8(v1[6], v1[7], v1[8], PC1);
    const float PA0 = ((oct & 4) ? v0[0] : 1.0f - v0[0])
                    * ((oct & 2) ? v0[1] : 1.0f - v0[1])
                    * ((oct & 1) ? v0[2] : 1.0f - v0[2]);
    const float PA1 = ((oct & 4) ? v1[0] : 1.0f - v1[0])
                    * ((oct & 2) ? v1[1] : 1.0f - v1[1])
                    * ((oct & 1) ? v1[2] : 1.0f - v1[2]);

    const float* sp = s_s + pixL * SROW + oct * AROW;
    float a0e = 0.0f, a0o = 0.0f, a1e = 0.0f, a1o = 0.0f;
#pragma unroll
    for (int b = 0; b < 8; b += 2) {
        float4 r0 = *(const float4*)(sp + b * 8);
        float4 r1 = *(const float4*)(sp + b * 8 + 4);
        float4 r2 = *(const float4*)(sp + b * 8 + 8);
        float4 r3 = *(const float4*)(sp + b * 8 + 12);

        float i00 = PC0[0] * r0.x;
        i00 = fmaf(PC0[1], r0.y, i00);
        i00 = fmaf(PC0[2], r0.z, i00);
        i00 = fmaf(PC0[3], r0.w, i00);
        i00 = fmaf(PC0[4], r1.x, i00);
        i00 = fmaf(PC0[5], r1.y, i00);
        i00 = fmaf(PC0[6], r1.z, i00);
        i00 = fmaf(PC0[7], r1.w, i00);
        float i10 = PC1[0] * r0.x;
        i10 = fmaf(PC1[1], r0.y, i10);
        i10 = fmaf(PC1[2], r0.z, i10);
        i10 = fmaf(PC1[3], r0.w, i10);
        i10 = fmaf(PC1[4], r1.x, i10);
        i10 = fmaf(PC1[5], r1.y, i10);
        i10 = fmaf(PC1[6], r1.z, i10);
        i10 = fmaf(PC1[7], r1.w, i10);
        float i01 = PC0[0] * r2.x;
        i01 = fmaf(PC0[1], r2.y, i01);
        i01 = fmaf(PC0[2], r2.z, i01);
        i01 = fmaf(PC0[3], r2.w, i01);
        i01 = fmaf(PC0[4], r3.x, i01);
        i01 = fmaf(PC0[5], r3.y, i01);
        i01 = fmaf(PC0[6], r3.z, i01);
        i01 = fmaf(PC0[7], r3.w, i01);
        float i11 = PC1[0] * r2.x;
        i11 = fmaf(PC1[1], r2.y, i11);
        i11 = fmaf(PC1[2], r2.z, i11);
        i11 = fmaf(PC1[3], r2.w, i11);
        i11 = fmaf(PC1[4], r3.x, i11);
        i11 = fmaf(PC1[5], r3.y, i11);
        i11 = fmaf(PC1[6], r3.z, i11);
        i11 = fmaf(PC1[7], r3.w, i11);

        a0e = fmaf(PB0[b], i00, a0e);
        a1e = fmaf(PB1[b], i10, a1e);
        a0o = fmaf(PB0[b + 1], i01, a0o);
        a1o = fmaf(PB1[b + 1], i11, a1o);
    }
    float acc0 = PA0 * (a0e + a0o);
    float acc1 = PA1 * (a1e + a1o);

#pragma unroll
    for (int d = 1; d <= 4; d <<= 1) {
        acc0 += __shfl_xor_sync(0xffffffffu, acc0, d);
        acc1 += __shfl_xor_sync(0xffffffffu, acc1, d);
    }

    if (oct == 0) {
        dst[b0 * (HH * WW) + pixel] = fminf(fmaxf(acc0, 0.0f), 1.0f);
        dst[b1 * (HH * WW) + pixel] = fminf(fmaxf(acc1, 0.0f), 1.0f);
    }

    // ---- publish: this tile's layer-L outputs are visible ----
    if (L < NLAYERS - 1) {
        __threadfence();
        __syncthreads();
        if (tid == 0) atomicMax(&g_flag[L][bid], target);
    }
}

static inline void launch_pdl(const float* src, const float* tg, float* dst, int L) {
    cudaLaunchConfig_t cfg = {};
    cfg.gridDim = dim3(GRID, 1, 1);
    cfg.blockDim = dim3(THREADS, 1, 1);
    cfg.dynamicSmemBytes = 0;
    cfg.stream = 0;
    cudaLaunchAttribute attr[1];
    attr[0].id = cudaLaunchAttributeProgrammaticStreamSerialization;
    attr[0].val.programmaticStreamSerializationAllowed = 1;
    cfg.attrs = attr;
    cfg.numAttrs = 1;
    cudaLaunchKernelEx(&cfg, asic_layer, src, tg, dst, L);
}

extern "C" void kernel_launch(void* const* d_in, const int* in_sizes, int n_in,
                              void* d_out, int out_size) {
    // Identify inputs by size (x: 16384, tg: 2097152)
    const float* x  = (const float*)d_in[0];
    const float* tg = (const float*)d_in[1];
    if (n_in >= 2 && in_sizes[0] > in_sizes[1]) {
        x  = (const float*)d_in[1];
        tg = (const float*)d_in[0];
    }
    float* out = (float*)d_out;

    float* st;
    cudaGetSymbolAddress((void**)&st, g_state);
    float* s0 = st;
    float* s1 = st + BB * HH * WW;
    float* s2 = st + 2 * BB * HH * WW;

    launch_pdl(x,  tg + 0 * LHW, s0, 0);
    launch_pdl(s0, tg + 1 * LHW, s1, 1);
    launch_pdl(s1, tg + 2 * LHW, s2, 2);
    launch_pdl(s2, tg + 3 * LHW, out, 3);
}